// round 10
// baseline (speedup 1.0000x reference)
#include <cuda_runtime.h>
#include <cuda_bf16.h>

#define NCLASS 100
#define NCPAD  101               // +1 dummy class for duplicate-redirect
#define NFEAT  64
#define NWARPS 4                 // warps per block; each warp owns a private copy
#define TPB    (NWARPS * 32)
#define CE     (NCLASS * 32)     // global scratch entries (float4 per class x lanepair)
#define CEP    (NCPAD * 32)      // smem entries per copy (padded)
#define BATCH  16

// float4 = {sum_even, sumsq_even, sum_odd, sumsq_odd}
__device__ float4       g_acc[CE];       // zero-initialized at module load
__device__ unsigned int g_cnt[NCLASS];   // final_kernel resets both every call

// One warp = one group with a private smem float4 acc[101][32]; lane l owns
// feature columns (2l, 2l+1). Per row: ONE warp LDG.64 + (per row-pair) two
// LDS.128/STS.128 -> ~3 memory instrs/row/SM vs 6 before: tests the
// LSU-issue-bound hypothesis. Depth-3 pipeline keeps ~32-48 LDGs in flight.
__global__ void __launch_bounds__(TPB, 1)
accum_kernel(const float* __restrict__ x, const int* __restrict__ t, int nrows) {
    extern __shared__ float4 smem[];
    const int wid = threadIdx.x >> 5;
    const int l   = threadIdx.x & 31;
    float4* acc = smem + wid * CEP;
    unsigned int* cnt = (unsigned int*)(smem + NWARPS * CEP);

    for (int i = threadIdx.x; i < NWARPS * CEP; i += TPB)
        smem[i] = make_float4(0.f, 0.f, 0.f, 0.f);
    for (int i = threadIdx.x; i < NCLASS; i += TPB) cnt[i] = 0u;
    __syncthreads();

    const int gid     = blockIdx.x * NWARPS + wid;
    const int ngroups = gridDim.x * NWARPS;
    const int nchunks = (nrows + BATCH - 1) / BATCH;
    const float2* x2 = (const float2*)x;

    float2 v0[BATCH], v1[BATCH], v2[BATCH];
    int c0, c1, c2;

    auto load_chunk = [&](int ci, int& c_lane, float2* v) {
        const int r0 = ci * BATCH;
        const int nv = min(BATCH, nrows - r0);
        c_lane = 0;
        if (l < nv) c_lane = __ldcs(t + r0 + l);           // one 64B coalesced LDG
        if (l < nv) atomicAdd(&cnt[c_lane], 1u);           // spread-addr ATOMS, 1/chunk
        if (nv == BATCH) {
            #pragma unroll
            for (int b = 0; b < BATCH; b++)
                v[b] = __ldcs(x2 + (size_t)(r0 + b) * 32 + l);  // 256B/warp coalesced
        } else {
            #pragma unroll
            for (int b = 0; b < BATCH; b++)
                v[b] = (b < nv) ? __ldcs(x2 + (size_t)(r0 + b) * 32 + l)
                                : make_float2(0.f, 0.f);
        }
    };

    auto accum_chunk = [&](int c_lane, const float2* v) {
        int carr[BATCH];
        #pragma unroll
        for (int b = 0; b < BATCH; b++)
            carr[b] = __shfl_sync(0xffffffffu, c_lane, b);
        #pragma unroll
        for (int b = 0; b < BATCH; b += 2) {
            const float2 va = v[b], vb = v[b + 1];
            const bool dup = (carr[b] == carr[b + 1]);
            const int idx0 = carr[b] * 32 + l;
            const int idx1 = (dup ? NCLASS : carr[b + 1]) * 32 + l;  // dummy if dup
            // merged contributions for slot0; zeroed for slot1 when dup
            const float sb_x = dup ? vb.x : 0.f, sb_y = dup ? vb.y : 0.f;
            const float s0x = va.x + sb_x;
            const float q0x = fmaf(va.x, va.x, dup ? vb.x * vb.x : 0.f);
            const float s0y = va.y + sb_y;
            const float q0y = fmaf(va.y, va.y, dup ? vb.y * vb.y : 0.f);
            const float s1x = dup ? 0.f : vb.x;
            const float q1x = dup ? 0.f : vb.x * vb.x;
            const float s1y = dup ? 0.f : vb.y;
            const float q1y = dup ? 0.f : vb.y * vb.y;
            // idx0 != idx1 always -> both RMWs independent, LDS latencies overlap
            float4 a0 = acc[idx0];
            float4 a1 = acc[idx1];
            a0.x += s0x; a0.y += q0x; a0.z += s0y; a0.w += q0y;
            a1.x += s1x; a1.y += q1x; a1.z += s1y; a1.w += q1y;
            acc[idx0] = a0;
            acc[idx1] = a1;
        }
    };

    // Depth-3 rotated pipeline: load(ca+2ng) in flight while accum(ca).
    int ca = gid;
    int cl = gid + 2 * ngroups;
    bool run = ca < nchunks;
    if (run)                    load_chunk(ca, c0, v0);
    if (ca + ngroups < nchunks) load_chunk(ca + ngroups, c1, v1);
    while (run) {
        if (cl < nchunks) load_chunk(cl, c2, v2);
        cl += ngroups;
        accum_chunk(c0, v0);
        ca += ngroups; run = ca < nchunks;
        if (!run) break;

        if (cl < nchunks) load_chunk(cl, c0, v0);
        cl += ngroups;
        accum_chunk(c1, v1);
        ca += ngroups; run = ca < nchunks;
        if (!run) break;

        if (cl < nchunks) load_chunk(cl, c1, v1);
        cl += ngroups;
        accum_chunk(c2, v2);
        ca += ngroups; run = ca < nchunks;
    }
    __syncthreads();

    // Reduce the 4 warp copies (real classes only) and flush to global.
    for (int i = threadIdx.x; i < CE; i += TPB) {
        float4 s = make_float4(0.f, 0.f, 0.f, 0.f);
        #pragma unroll
        for (int g = 0; g < NWARPS; g++) {
            const float4 a = smem[g * CEP + i];
            s.x += a.x; s.y += a.y; s.z += a.z; s.w += a.w;
        }
        atomicAdd(&g_acc[i].x, s.x);
        atomicAdd(&g_acc[i].y, s.y);
        atomicAdd(&g_acc[i].z, s.z);
        atomicAdd(&g_acc[i].w, s.w);
    }
    for (int i = threadIdx.x; i < NCLASS; i += TPB)
        atomicAdd(&g_cnt[i], cnt[i]);
}

// Reads AND resets global scratch (device globals start zero-initialized,
// so every graph replay sees identical initial state).
__global__ void final_kernel(float* __restrict__ out) {
    __shared__ double red[256];
    __shared__ float ncache[NCLASS];
    for (int i = threadIdx.x; i < NCLASS; i += 256) {
        ncache[i] = (float)g_cnt[i];
        g_cnt[i] = 0u;
    }
    __syncthreads();
    double accd = 0.0;
    for (int i = threadIdx.x; i < CE; i += 256) {
        const int c = i >> 5;
        const double n = (double)ncache[c];
        const float4 a = g_acc[i];
        g_acc[i] = make_float4(0.f, 0.f, 0.f, 0.f);
        accd += ((double)a.y - (double)a.x * (double)a.x / n) / (n - 1.0);
        accd += ((double)a.w - (double)a.z * (double)a.z / n) / (n - 1.0);
    }
    red[threadIdx.x] = accd;
    __syncthreads();
    #pragma unroll
    for (int off = 128; off > 0; off >>= 1) {
        if ((int)threadIdx.x < off) red[threadIdx.x] += red[threadIdx.x + off];
        __syncthreads();
    }
    if (threadIdx.x == 0) out[0] = (float)(red[0] / (double)NCLASS);
}

extern "C" void kernel_launch(void* const* d_in, const int* in_sizes, int n_in,
                              void* d_out, int out_size) {
    const float* x = (const float*)d_in[0];   // (N, 64) fp32
    const int*   t = (const int*)d_in[1];     // (N,)    int32
    const int nrows = in_sizes[0] / NFEAT;
    float* out = (float*)d_out;

    int nsm = 148;
    cudaDeviceGetAttribute(&nsm, cudaDevAttrMultiProcessorCount, 0);

    const size_t smem_bytes = (size_t)NWARPS * CEP * sizeof(float4)
                            + (size_t)NCLASS * sizeof(unsigned int);
    cudaFuncSetAttribute(accum_kernel, cudaFuncAttributeMaxDynamicSharedMemorySize,
                         (int)smem_bytes);

    accum_kernel<<<nsm, TPB, smem_bytes>>>(x, t, nrows);
    final_kernel<<<1, 256>>>(out);
}

// round 15
// speedup vs baseline: 1.4357x; 1.4357x over previous
#include <cuda_runtime.h>
#include <cuda_bf16.h>

#define NCLASS 100
#define NCPAD  101               // +1 dummy class for duplicate-redirect
#define NFEAT  64
#define GROUPS 4
#define TPB    256
#define CP     (NCLASS * NFEAT)  // 6400 (global scratch, real classes only)
#define CPP    (NCPAD * NFEAT)   // 6464 (smem, padded)
#define BATCH  16

__device__ float2       g_acc[CP];      // zero-init at load; reset by final1
__device__ unsigned int g_cnt[NCLASS];  // reset by final2
__device__ double       g_part[NCLASS];

// Pad no-ops so ncu (-s 5 -c 1, 5 launches/call) profiles accum_kernel.
__global__ void pad_kernel() {}

// 64-thread group owns a private smem float2 acc[101][64]; thread p owns
// column p. Pair-merged RMWs (duplicate classes within a row-pair are merged
// in registers, the duplicate redirected to dummy class 100) so the two smem
// RMW addresses are provably distinct and their LDS latencies overlap.
// Depth-2 double-buffered 16-row chunks keep ~17-33 LDGs/warp in flight.
__global__ void __launch_bounds__(TPB, 1)
accum_kernel(const float* __restrict__ x, const int* __restrict__ t, int nrows) {
    extern __shared__ float2 smem[];
    const int group = threadIdx.x >> 6;
    const int p     = threadIdx.x & 63;
    const int w     = (threadIdx.x >> 5) & 1;
    const int l     = threadIdx.x & 31;
    float2* acc = smem + group * CPP;
    unsigned int* cnt = (unsigned int*)(smem + GROUPS * CPP);

    for (int i = threadIdx.x; i < GROUPS * CPP; i += TPB) smem[i] = make_float2(0.f, 0.f);
    for (int i = threadIdx.x; i < NCLASS; i += TPB) cnt[i] = 0u;
    __syncthreads();

    const int gid     = blockIdx.x * GROUPS + group;
    const int ngroups = gridDim.x * GROUPS;
    const int nchunks = (nrows + BATCH - 1) / BATCH;

    float vs[BATCH], vs2[BATCH];
    int myc, myc2;

    auto load_chunk = [&](int ci, int& c_lane, float* v) {
        const int r0 = ci * BATCH;
        const int nv = min(BATCH, nrows - r0);
        c_lane = 0;
        if (l < nv) c_lane = __ldcs(t + r0 + l);           // one 64B coalesced LDG
        if (w == 0 && l < nv) atomicAdd(&cnt[c_lane], 1u); // spread-addr ATOMS, 1/chunk
        if (nv == BATCH) {
            #pragma unroll
            for (int b = 0; b < BATCH; b++)
                v[b] = __ldcs(x + (size_t)(r0 + b) * NFEAT + p);
        } else {
            #pragma unroll
            for (int b = 0; b < BATCH; b++)
                v[b] = (b < nv) ? __ldcs(x + (size_t)(r0 + b) * NFEAT + p) : 0.f;
        }
    };

    auto accum_chunk = [&](int c_lane, const float* v) {
        int carr[BATCH];
        #pragma unroll
        for (int b = 0; b < BATCH; b++)
            carr[b] = __shfl_sync(0xffffffffu, c_lane, b);
        #pragma unroll
        for (int b = 0; b < BATCH; b += 2) {
            const float va = v[b], vb = v[b + 1];
            const bool dup = (carr[b] == carr[b + 1]);
            const int idx0 = carr[b] * NFEAT + p;
            const int idx1 = (dup ? NCLASS : carr[b + 1]) * NFEAT + p;
            const float qb  = vb * vb;
            const float s0  = va + (dup ? vb : 0.f);
            const float q0  = fmaf(va, va, dup ? qb : 0.f);
            const float s1  = dup ? 0.f : vb;
            const float q1  = dup ? 0.f : qb;
            float2 a0 = acc[idx0];
            float2 a1 = acc[idx1];
            a0.x += s0;  a0.y += q0;
            a1.x += s1;  a1.y += q1;
            acc[idx0] = a0;
            acc[idx1] = a1;
        }
    };

    int ci = gid;
    if (ci < nchunks) {
        load_chunk(ci, myc, vs);
        while (true) {
            const int cn = ci + ngroups;
            if (cn < nchunks) {
                load_chunk(cn, myc2, vs2);   // LDGs in flight...
                accum_chunk(myc, vs);        // ...while smem RMWs run
                myc = myc2;
                #pragma unroll
                for (int b = 0; b < BATCH; b++) vs[b] = vs2[b];
                ci = cn;
            } else {
                accum_chunk(myc, vs);
                break;
            }
        }
    }
    __syncthreads();

    for (int i = threadIdx.x; i < CP; i += TPB) {
        float ts = 0.f, tss = 0.f;
        #pragma unroll
        for (int g = 0; g < GROUPS; g++) {
            ts  += smem[g * CPP + i].x;
            tss += smem[g * CPP + i].y;
        }
        atomicAdd(&g_acc[i].x, ts);
        atomicAdd(&g_acc[i].y, tss);
    }
    for (int i = threadIdx.x; i < NCLASS; i += TPB)
        atomicAdd(&g_cnt[i], cnt[i]);
}

// One block per class: warp-reduce 64 cells in fp64, 2 divides/class, and
// reset this class's scratch slice (keeps graph replays identical).
__global__ void final1_kernel() {
    const int c = blockIdx.x;
    const int l = threadIdx.x;   // 32 threads
    const float2 a = g_acc[c * NFEAT + l];
    const float2 b = g_acc[c * NFEAT + 32 + l];
    g_acc[c * NFEAT + l]      = make_float2(0.f, 0.f);
    g_acc[c * NFEAT + 32 + l] = make_float2(0.f, 0.f);
    double dss = (double)a.y + (double)b.y;                          // Σ ss
    double dsq = (double)a.x * a.x + (double)b.x * b.x;              // Σ s²
    #pragma unroll
    for (int off = 16; off > 0; off >>= 1) {
        dss += __shfl_down_sync(0xffffffffu, dss, off);
        dsq += __shfl_down_sync(0xffffffffu, dsq, off);
    }
    if (l == 0) {
        const double n = (double)g_cnt[c];
        g_part[c] = (dss - dsq / n) / (n - 1.0);
    }
}

__global__ void final2_kernel(float* __restrict__ out) {
    __shared__ double red[128];
    double v = (threadIdx.x < NCLASS) ? g_part[threadIdx.x] : 0.0;
    if (threadIdx.x < NCLASS) g_cnt[threadIdx.x] = 0u;   // reset counts
    red[threadIdx.x] = v;
    __syncthreads();
    #pragma unroll
    for (int off = 64; off > 0; off >>= 1) {
        if ((int)threadIdx.x < off) red[threadIdx.x] += red[threadIdx.x + off];
        __syncthreads();
    }
    if (threadIdx.x == 0) out[0] = (float)(red[0] / (double)NCLASS);
}

extern "C" void kernel_launch(void* const* d_in, const int* in_sizes, int n_in,
                              void* d_out, int out_size) {
    const float* x = (const float*)d_in[0];   // (N, 64) fp32
    const int*   t = (const int*)d_in[1];     // (N,)    int32
    const int nrows = in_sizes[0] / NFEAT;
    float* out = (float*)d_out;

    int nsm = 148;
    cudaDeviceGetAttribute(&nsm, cudaDevAttrMultiProcessorCount, 0);

    const size_t smem_bytes = (size_t)GROUPS * CPP * sizeof(float2)
                            + (size_t)NCLASS * sizeof(unsigned int);
    cudaFuncSetAttribute(accum_kernel, cudaFuncAttributeMaxDynamicSharedMemorySize,
                         (int)smem_bytes);

    accum_kernel<<<nsm, TPB, smem_bytes>>>(x, t, nrows);
    final1_kernel<<<NCLASS, 32>>>();
    final2_kernel<<<1, 128>>>(out);
    pad_kernel<<<1, 32>>>();   // 5 launches/call -> ncu -s 5 lands on accum
    pad_kernel<<<1, 32>>>();
}